// round 2
// baseline (speedup 1.0000x reference)
#include <cuda_runtime.h>
#include <math.h>

// Problem constants
#define BSZ   32
#define TLEN  1024
#define DIN   768
#define HD    768
#define G3    2304          // 3*HD
#define FCN   512
#define NOUTC 39

// ---------------------------------------------------------------------------
// Scratch (device globals; no allocation allowed)
// ---------------------------------------------------------------------------
__device__ float g_xproj[(size_t)BSZ * TLEN * G3];   // input projections [B,T,3H]
__device__ float g_hall [(size_t)BSZ * TLEN * HD];   // GRU outputs [B,T,H]
__device__ float g_fc   [(size_t)BSZ * TLEN * FCN];  // fc output

// Grid-barrier state (sense reversal). Both end at their initial values after
// every launch (even number of barriers per launch), so graph replays are
// deterministic.
__device__ unsigned g_count = 0;
__device__ unsigned g_sense = 0;

// ---------------------------------------------------------------------------
// Generic fp32 GEMM: C[M,N] = act(A[M,K] @ W[N,K]^T + bias[N])
// BM=BN=128, BK=8, 256 threads, 8x8 register micro-tile.
// ACT: 0 = none, 1 = SELU, 2 = tanh
// ---------------------------------------------------------------------------
template <int ACT>
__global__ __launch_bounds__(256) void gemm_bias_act(
    const float* __restrict__ A,
    const float* __restrict__ W,
    const float* __restrict__ bias,
    float* __restrict__ C,
    int M, int N, int K)
{
    __shared__ float As[8][128];
    __shared__ float Bs[8][128];

    const int tid  = threadIdx.x;
    const int m0   = blockIdx.y * 128;
    const int n0   = blockIdx.x * 128;

    const int lrow = tid >> 1;           // 0..127
    const int lk4  = (tid & 1) * 4;      // 0 or 4

    const int tx = tid & 15;             // 0..15 (n)
    const int ty = tid >> 4;             // 0..15 (m)

    float acc[8][8];
#pragma unroll
    for (int i = 0; i < 8; i++)
#pragma unroll
        for (int j = 0; j < 8; j++) acc[i][j] = 0.f;

    const float* Arow = A + (size_t)(m0 + lrow) * K + lk4;
    const float* Wrow = W + (size_t)(n0 + lrow) * K + lk4;
    const bool   wok  = (n0 + lrow) < N;

    for (int k0 = 0; k0 < K; k0 += 8) {
        float4 av = *(const float4*)(Arow + k0);
        float4 wv = make_float4(0.f, 0.f, 0.f, 0.f);
        if (wok) wv = *(const float4*)(Wrow + k0);

        __syncthreads();
        As[lk4 + 0][lrow] = av.x; As[lk4 + 1][lrow] = av.y;
        As[lk4 + 2][lrow] = av.z; As[lk4 + 3][lrow] = av.w;
        Bs[lk4 + 0][lrow] = wv.x; Bs[lk4 + 1][lrow] = wv.y;
        Bs[lk4 + 2][lrow] = wv.z; Bs[lk4 + 3][lrow] = wv.w;
        __syncthreads();

#pragma unroll
        for (int kk = 0; kk < 8; kk++) {
            float a[8], b[8];
            *(float4*)(a)     = *(const float4*)&As[kk][ty * 8];
            *(float4*)(a + 4) = *(const float4*)&As[kk][ty * 8 + 4];
            *(float4*)(b)     = *(const float4*)&Bs[kk][tx * 8];
            *(float4*)(b + 4) = *(const float4*)&Bs[kk][tx * 8 + 4];
#pragma unroll
            for (int i = 0; i < 8; i++)
#pragma unroll
                for (int j = 0; j < 8; j++)
                    acc[i][j] = fmaf(a[i], b[j], acc[i][j]);
        }
    }

    const float selu_scale = 1.0507009873554804934193349852946f;
    const float selu_alpha = 1.6732632423543772848170429916717f;

#pragma unroll
    for (int i = 0; i < 8; i++) {
        const int m = m0 + ty * 8 + i;
        float* crow = C + (size_t)m * N;
#pragma unroll
        for (int j = 0; j < 8; j++) {
            const int n = n0 + tx * 8 + j;
            if (n < N) {
                float v = acc[i][j] + bias[n];
                if (ACT == 1) {
                    v = selu_scale * (v > 0.f ? v : selu_alpha * (expf(v) - 1.f));
                } else if (ACT == 2) {
                    v = tanhf(v);
                }
                crow[n] = v;
            }
        }
    }
}

// ---------------------------------------------------------------------------
// Persistent GRU layer kernel: runs ALL 1024 timesteps in one launch.
// 96 blocks (one per SM, co-resident), each owns NU=8 hidden units.
// w_hh slice (24x768) loaded into smem ONCE. Per step:
//   stage h_{t-1} -> smem, GEMM (8x6 micro-tile, 16-way K split),
//   smem reduction, gates, write h_t, grid barrier.
// Barrier count per launch = 1024 (even) -> g_sense returns to 0.
// ---------------------------------------------------------------------------
#define NBLK      96
#define NU        8
#define NROWS     24            // 3*NU
#define HPITCH    769           // 768 + 1 (conflict-free strided reads)
#define RPITCH    17            // 16 + 1
#define SH_H_FL   (32 * HPITCH)             // 24608 floats
#define SH_W_FL   (NROWS * HPITCH)          // 18456 floats
#define SH_R_FL   (768 * RPITCH)            // 13056 floats
#define STEP_SMEM ((SH_H_FL + SH_W_FL + SH_R_FL) * sizeof(float))  // 224480 B

__device__ __forceinline__ void grid_barrier(unsigned& lsense)
{
    __syncthreads();
    if (threadIdx.x == 0) {
        const unsigned s = (lsense ^= 1u);
        __threadfence();
        const unsigned old = atomicAdd(&g_count, 1u);
        if (old == NBLK - 1) {
            g_count = 0;                 // safe: nobody touches count until sense flips
            __threadfence();
            atomicExch(&g_sense, s);     // release
        } else {
            while (*(volatile unsigned*)&g_sense != s) { }
            __threadfence();             // acquire
        }
    }
    __syncthreads();
}

__global__ __launch_bounds__(256) void gru_layer_persistent(
    const float* __restrict__ xproj,   // [B,T,3H] (gi, b_ih already folded in)
    const float* __restrict__ w_hh,    // [3H, H]
    const float* __restrict__ b_hh,    // [3H]
    float* __restrict__ h_all)         // [B,T,H]
{
    extern __shared__ float sm[];
    float* sh_h = sm;                       // [32][HPITCH]
    float* sh_w = sm + SH_H_FL;             // [24][HPITCH]
    float* sh_r = sm + SH_H_FL + SH_W_FL;   // [768][RPITCH]

    const int tid = threadIdx.x;
    const int u0  = blockIdx.x * NU;

    // --- one-time: load w_hh slice (row lr -> gate = lr>>3, unit = lr&7) ---
    for (int i = tid; i < NROWS * 192; i += 256) {   // 192 float4 per row
        const int lr = i / 192;
        const int k4 = (i % 192) * 4;
        const int gate = lr >> 3;
        const int u    = lr & 7;
        const float4 v = *(const float4*)(w_hh + (size_t)(gate * HD + u0 + u) * HD + k4);
        float* dst = sh_w + lr * HPITCH + k4;
        dst[0] = v.x; dst[1] = v.y; dst[2] = v.z; dst[3] = v.w;
    }

    // GEMM-phase decode
    const int bq = tid & 3;          // 4 groups of 8 batches
    const int rq = (tid >> 2) & 3;   // 4 groups of 6 rows
    const int ks = tid >> 4;         // 16 K-slices of 48
    const float* hp = sh_h + (bq * 8) * HPITCH;
    const float* wp = sh_w + (rq * 6) * HPITCH;
    const int kbeg = ks * 48;

    // Gate-phase decode + per-thread constants
    const int bg = tid >> 3;         // batch 0..31
    const int ug = tid & 7;          // unit 0..7
    const float bias_r = b_hh[u0 + ug];
    const float bias_z = b_hh[HD + u0 + ug];
    const float bias_n = b_hh[2 * HD + u0 + ug];
    const size_t hrow  = (size_t)bg * TLEN;   // row base into [B*T] matrices

    unsigned lsense = 0;

    for (int t = 0; t < TLEN; t++) {
        // --- stage h_{t-1} ---
        if (t == 0) {
            for (int i = tid; i < 32 * 192; i += 256) {
                const int b  = i / 192;
                const int k4 = (i % 192) * 4;
                float* dst = sh_h + b * HPITCH + k4;
                dst[0] = 0.f; dst[1] = 0.f; dst[2] = 0.f; dst[3] = 0.f;
            }
        } else {
            for (int i = tid; i < 32 * 192; i += 256) {
                const int b  = i / 192;
                const int k4 = (i % 192) * 4;
                const float4 v = *(const float4*)(h_all + ((size_t)b * TLEN + (t - 1)) * HD + k4);
                float* dst = sh_h + b * HPITCH + k4;
                dst[0] = v.x; dst[1] = v.y; dst[2] = v.z; dst[3] = v.w;
            }
        }
        __syncthreads();

        // prefetch gate inputs (latency overlaps the GEMM phase)
        const size_t xbase = (hrow + t) * G3 + (u0 + ug);
        const float gi_r = xproj[xbase];
        const float gi_z = xproj[xbase + HD];
        const float gi_n = xproj[xbase + 2 * HD];
        const float hprev = sh_h[bg * HPITCH + u0 + ug];

        // --- partial GEMM: 8 batches x 6 rows over a 48-wide K slice ---
        float acc[8][6];
#pragma unroll
        for (int i = 0; i < 8; i++)
#pragma unroll
            for (int j = 0; j < 6; j++) acc[i][j] = 0.f;

#pragma unroll 4
        for (int k = kbeg; k < kbeg + 48; k++) {
            float hr[8];
#pragma unroll
            for (int i = 0; i < 8; i++) hr[i] = hp[i * HPITCH + k];
#pragma unroll
            for (int j = 0; j < 6; j++) {
                const float wv = wp[j * HPITCH + k];
#pragma unroll
                for (int i = 0; i < 8; i++) acc[i][j] = fmaf(hr[i], wv, acc[i][j]);
            }
        }

        // --- dump partials: r[out][ks], out = lr*32 + b ---
#pragma unroll
        for (int j = 0; j < 6; j++) {
            const int lr = rq * 6 + j;
#pragma unroll
            for (int i = 0; i < 8; i++) {
                const int b = bq * 8 + i;
                sh_r[(lr * 32 + b) * RPITCH + ks] = acc[i][j];
            }
        }
        __syncthreads();

        // --- gates: one (batch, unit) per thread ---
        {
            float gh[3];
#pragma unroll
            for (int g = 0; g < 3; g++) {
                const int out = (g * 8 + ug) * 32 + bg;
                float s = 0.f;
#pragma unroll
                for (int p = 0; p < 16; p++) s += sh_r[out * RPITCH + p];
                gh[g] = s;
            }
            const float r = 1.f / (1.f + expf(-(gi_r + gh[0] + bias_r)));
            const float z = 1.f / (1.f + expf(-(gi_z + gh[1] + bias_z)));
            const float n = tanhf(gi_n + r * (gh[2] + bias_n));
            const float hnew = (1.f - z) * n + z * hprev;

            h_all[(hrow + t) * HD + (u0 + ug)] = hnew;
        }

        // --- make h_t visible to all blocks ---
        grid_barrier(lsense);
    }
}

// ---------------------------------------------------------------------------
// Launch: 6 graph nodes total.
// ---------------------------------------------------------------------------
extern "C" void kernel_launch(void* const* d_in, const int* in_sizes, int n_in,
                              void* d_out, int out_size)
{
    const float* features = (const float*)d_in[0];
    // d_in[1] = padding_mask (unused by forward math)
    const float* w_ih0 = (const float*)d_in[2];
    const float* w_hh0 = (const float*)d_in[3];
    const float* b_ih0 = (const float*)d_in[4];
    const float* b_hh0 = (const float*)d_in[5];
    const float* w_ih1 = (const float*)d_in[6];
    const float* w_hh1 = (const float*)d_in[7];
    const float* b_ih1 = (const float*)d_in[8];
    const float* b_hh1 = (const float*)d_in[9];
    const float* fc_w  = (const float*)d_in[10];
    const float* fc_b  = (const float*)d_in[11];
    const float* out_w = (const float*)d_in[12];
    const float* out_b = (const float*)d_in[13];

    float *xproj, *hall, *fcb;
    cudaGetSymbolAddress((void**)&xproj, g_xproj);
    cudaGetSymbolAddress((void**)&hall,  g_hall);
    cudaGetSymbolAddress((void**)&fcb,   g_fc);

    static bool attr_set = false;
    if (!attr_set) {
        cudaFuncSetAttribute(gru_layer_persistent,
                             cudaFuncAttributeMaxDynamicSharedMemorySize,
                             (int)STEP_SMEM);
        attr_set = true;
    }

    const int M = BSZ * TLEN;                 // 32768

    // Layer 0: input projection (bias b_ih folded in)
    {
        dim3 grid(G3 / 128, M / 128);
        gemm_bias_act<0><<<grid, 256>>>(features, w_ih0, b_ih0, xproj, M, G3, DIN);
    }
    // Layer 0: full recurrence in one persistent kernel
    gru_layer_persistent<<<NBLK, 256, STEP_SMEM>>>(xproj, w_hh0, b_hh0, hall);

    // Layer 1: input projection (reads layer-0 h_all, overwrites xproj)
    {
        dim3 grid(G3 / 128, M / 128);
        gemm_bias_act<0><<<grid, 256>>>(hall, w_ih1, b_ih1, xproj, M, G3, HD);
    }
    // Layer 1: recurrence (overwrites h_all in place)
    gru_layer_persistent<<<NBLK, 256, STEP_SMEM>>>(xproj, w_hh1, b_hh1, hall);

    // fc + SELU
    {
        dim3 grid(FCN / 128, M / 128);
        gemm_bias_act<1><<<grid, 256>>>(hall, fc_w, fc_b, fcb, M, FCN, HD);
    }
    // out_proj + tanh
    {
        dim3 grid((NOUTC + 127) / 128, M / 128);
        gemm_bias_act<2><<<grid, 256>>>(fcb, out_w, out_b, (float*)d_out, M, NOUTC, FCN);
    }
}

// round 3
// speedup vs baseline: 1.0090x; 1.0090x over previous
#include <cuda_runtime.h>
#include <math.h>

// Problem constants
#define BSZ   32
#define TLEN  1024
#define DIN   768
#define HD    768
#define G3    2304          // 3*HD
#define FCN   512
#define NOUTC 39

typedef unsigned long long ull;

// ---------------------------------------------------------------------------
// Scratch (device globals; no allocation allowed)
// ---------------------------------------------------------------------------
__device__ float g_xproj[(size_t)BSZ * TLEN * G3];   // input projections [B,T,3H]
__device__ float g_hall [(size_t)BSZ * TLEN * HD];   // GRU outputs [B,T,H]
__device__ float g_fc   [(size_t)BSZ * TLEN * FCN];  // fc output

// Grid-barrier flags: monotonically increasing, never reset -> deterministic
// across graph replays (all flags equal at every launch boundary).
__device__ unsigned g_flags[96];

// ---------------------------------------------------------------------------
// Packed fp32x2 FMA (Blackwell full-rate FP32 path; ptxas never emits it)
// ---------------------------------------------------------------------------
__device__ __forceinline__ void fma2(ull& d, ull a, ull b) {
    asm("fma.rn.f32x2 %0, %1, %2, %0;" : "+l"(d) : "l"(a), "l"(b));
}
__device__ __forceinline__ ull pack2(float lo, float hi) {
    ull d;
    asm("mov.b64 %0, {%1, %2};" : "=l"(d) : "f"(lo), "f"(hi));
    return d;
}
__device__ __forceinline__ float2 unpack2(ull v) {
    float2 r;
    asm("mov.b64 {%0, %1}, %2;" : "=f"(r.x), "=f"(r.y) : "l"(v));
    return r;
}

// ---------------------------------------------------------------------------
// Generic fp32 GEMM: C[M,N] = act(A[M,K] @ W[N,K]^T + bias[N])
// BM=BN=128, BK=8, 256 threads. Micro-tile 8x8 split as (4+4)x(4+4) so smem
// reads are 16B-stride conflict-free. Inner math in FFMA2 (n-paired).
// ACT: 0 = none, 1 = SELU, 2 = tanh
// ---------------------------------------------------------------------------
template <int ACT>
__global__ __launch_bounds__(256) void gemm_bias_act(
    const float* __restrict__ A,
    const float* __restrict__ W,
    const float* __restrict__ bias,
    float* __restrict__ C,
    int M, int N, int K)
{
    __shared__ float As[8][128];
    __shared__ float Bs[8][128];

    const int tid  = threadIdx.x;
    const int m0   = blockIdx.y * 128;
    const int n0   = blockIdx.x * 128;

    const int lrow = tid >> 1;           // 0..127
    const int lk4  = (tid & 1) * 4;      // 0 or 4

    const int tx = tid & 15;             // n group
    const int ty = tid >> 4;             // m group

    ull acc2[8][4];                      // [m][n-pair], n pairs adjacent
#pragma unroll
    for (int i = 0; i < 8; i++)
#pragma unroll
        for (int j = 0; j < 4; j++) acc2[i][j] = 0ull;

    const float* Arow = A + (size_t)(m0 + lrow) * K + lk4;
    const float* Wrow = W + (size_t)(n0 + lrow) * K + lk4;
    const bool   wok  = (n0 + lrow) < N;

    for (int k0 = 0; k0 < K; k0 += 8) {
        float4 av = *(const float4*)(Arow + k0);
        float4 wv = make_float4(0.f, 0.f, 0.f, 0.f);
        if (wok) wv = *(const float4*)(Wrow + k0);

        __syncthreads();
        As[lk4 + 0][lrow] = av.x; As[lk4 + 1][lrow] = av.y;
        As[lk4 + 2][lrow] = av.z; As[lk4 + 3][lrow] = av.w;
        Bs[lk4 + 0][lrow] = wv.x; Bs[lk4 + 1][lrow] = wv.y;
        Bs[lk4 + 2][lrow] = wv.z; Bs[lk4 + 3][lrow] = wv.w;
        __syncthreads();

#pragma unroll
        for (int kk = 0; kk < 8; kk++) {
            float a[8];
            *(float4*)(a)     = *(const float4*)&As[kk][ty * 4];
            *(float4*)(a + 4) = *(const float4*)&As[kk][64 + ty * 4];
            ulonglong2 b01 = *(const ulonglong2*)&Bs[kk][tx * 4];
            ulonglong2 b23 = *(const ulonglong2*)&Bs[kk][64 + tx * 4];
            ull bb[4] = { b01.x, b01.y, b23.x, b23.y };
            ull aa[8];
#pragma unroll
            for (int i = 0; i < 8; i++) aa[i] = pack2(a[i], a[i]);
#pragma unroll
            for (int i = 0; i < 8; i++)
#pragma unroll
                for (int j = 0; j < 4; j++)
                    fma2(acc2[i][j], aa[i], bb[j]);
        }
    }

    const float selu_scale = 1.0507009873554804934193349852946f;
    const float selu_alpha = 1.6732632423543772848170429916717f;

#pragma unroll
    for (int i = 0; i < 8; i++) {
        const int m = m0 + ((i < 4) ? (ty * 4 + i) : (64 + ty * 4 + i - 4));
        float* crow = C + (size_t)m * N;
#pragma unroll
        for (int j = 0; j < 4; j++) {
            const int nf = n0 + ((j < 2) ? (tx * 4 + j * 2)
                                         : (64 + tx * 4 + (j - 2) * 2));
            float2 v = unpack2(acc2[i][j]);
            float vals[2] = { v.x, v.y };
#pragma unroll
            for (int s = 0; s < 2; s++) {
                const int n = nf + s;
                if (n < N) {
                    float val = vals[s] + bias[n];
                    if (ACT == 1) {
                        val = selu_scale * (val > 0.f ? val
                                                      : selu_alpha * (expf(val) - 1.f));
                    } else if (ACT == 2) {
                        val = tanhf(val);
                    }
                    crow[n] = val;
                }
            }
        }
    }
}

// ---------------------------------------------------------------------------
// Persistent GRU layer kernel: all 1024 timesteps in one launch.
// 96 co-resident blocks, each owns NU=8 hidden units (24 gh rows).
// Per step: stage h_{t-1} (global->smem, float4), GEMM with FFMA2 k-pairs
// (8 batch x 6 row micro-tile, 16 interleaved k-slices), smem K-reduction,
// gates, flag-array grid barrier.
// ---------------------------------------------------------------------------
#define NBLK      96
#define NU        8
#define NROWS     24                        // 3*NU
#define HPITCH    772                       // 768 + 4 (16B-aligned rows)
#define RPITCH    17
#define SH_H_FL   (32 * HPITCH)             // 24704
#define SH_W_FL   (NROWS * HPITCH)          // 18528
#define SH_R_FL   (32 * NROWS * RPITCH)     // 13056
#define STEP_SMEM ((SH_H_FL + SH_W_FL + SH_R_FL) * sizeof(float))  // 225152 B

__global__ __launch_bounds__(256) void gru_layer_persistent(
    const float* __restrict__ xproj,   // [B,T,3H] (gi, b_ih already folded in)
    const float* __restrict__ w_hh,    // [3H, H]
    const float* __restrict__ b_hh,    // [3H]
    float* __restrict__ h_all)         // [B,T,H]
{
    extern __shared__ float sm[];
    float* sh_h = sm;                       // [32][HPITCH]
    float* sh_w = sm + SH_H_FL;             // [24][HPITCH]
    float* sh_r = sm + SH_H_FL + SH_W_FL;   // [32*24][RPITCH slots]

    const int tid = threadIdx.x;
    const int u0  = blockIdx.x * NU;

    // Flag base: all flags equal at launch start (monotonic protocol)
    const unsigned flag_base = g_flags[blockIdx.x];

    // --- one-time: load w_hh slice (row lr -> gate = lr>>3, unit = lr&7) ---
    for (int i = tid; i < NROWS * 192; i += 256) {   // 192 float4 per row
        const int lr = i / 192;
        const int k4 = (i % 192) * 4;
        const int gate = lr >> 3;
        const int u    = lr & 7;
        const float4 v = *(const float4*)(w_hh + (size_t)(gate * HD + u0 + u) * HD + k4);
        float* dst = sh_w + lr * HPITCH + k4;
        dst[0] = v.x; dst[1] = v.y; dst[2] = v.z; dst[3] = v.w;
    }

    // GEMM-phase decode: tid = ks (low 4) | bq (2) | rq (2)
    const int ks = tid & 15;          // 16 interleaved k-slices
    const int bq = (tid >> 4) & 3;    // 4 groups of 8 batches
    const int rq = tid >> 6;          // 4 groups of 6 rows
    const float* hp = sh_h + (bq * 8) * HPITCH + ks * 4;
    const float* wp = sh_w + (rq * 6) * HPITCH + ks * 4;

    // Gate-phase decode
    const int bg = tid >> 3;          // batch 0..31
    const int ug = tid & 7;           // unit 0..7
    const float bias_r = b_hh[u0 + ug];
    const float bias_z = b_hh[HD + u0 + ug];
    const float bias_n = b_hh[2 * HD + u0 + ug];
    const size_t hrow  = (size_t)bg * TLEN;

    for (int t = 0; t < TLEN; t++) {
        // --- stage h_{t-1} (t=0: zeros) ---
        if (t == 0) {
            for (int i = tid; i < 32 * 192; i += 256) {
                const int b  = i / 192;
                const int k4 = (i % 192) * 4;
                float* dst = sh_h + b * HPITCH + k4;
                dst[0] = 0.f; dst[1] = 0.f; dst[2] = 0.f; dst[3] = 0.f;
            }
        } else {
            for (int i = tid; i < 32 * 192; i += 256) {
                const int b  = i / 192;
                const int k4 = (i % 192) * 4;
                const float4 v = *(const float4*)(h_all + ((size_t)b * TLEN + (t - 1)) * HD + k4);
                float* dst = sh_h + b * HPITCH + k4;
                dst[0] = v.x; dst[1] = v.y; dst[2] = v.z; dst[3] = v.w;
            }
        }
        __syncthreads();

        // prefetch gate inputs (latency hidden under GEMM phase)
        const size_t xbase = (hrow + t) * G3 + (u0 + ug);
        const float gi_r = xproj[xbase];
        const float gi_z = xproj[xbase + HD];
        const float gi_n = xproj[xbase + 2 * HD];
        const float hprev = sh_h[bg * HPITCH + u0 + ug];

        // --- partial GEMM: 8 batches x 6 rows, k = 4*ks + 64*j (+0..3) ---
        ull acc2[8][6];
#pragma unroll
        for (int i = 0; i < 8; i++)
#pragma unroll
            for (int j = 0; j < 6; j++) acc2[i][j] = 0ull;

#pragma unroll
        for (int j = 0; j < 12; j++) {
            const int kb = j * 64;
            ulonglong2 h2[8];
            ulonglong2 w2[6];
#pragma unroll
            for (int i = 0; i < 8; i++)
                h2[i] = *(const ulonglong2*)(hp + i * HPITCH + kb);
#pragma unroll
            for (int jj = 0; jj < 6; jj++)
                w2[jj] = *(const ulonglong2*)(wp + jj * HPITCH + kb);
#pragma unroll
            for (int i = 0; i < 8; i++)
#pragma unroll
                for (int jj = 0; jj < 6; jj++) {
                    fma2(acc2[i][jj], h2[i].x, w2[jj].x);
                    fma2(acc2[i][jj], h2[i].y, w2[jj].y);
                }
        }

        // --- dump partials: sh_r[(b*24 + lr)*RPITCH + ks] ---
#pragma unroll
        for (int i = 0; i < 8; i++) {
            const int b = bq * 8 + i;
#pragma unroll
            for (int jj = 0; jj < 6; jj++) {
                const int lr = rq * 6 + jj;
                float2 p = unpack2(acc2[i][jj]);
                sh_r[(b * NROWS + lr) * RPITCH + ks] = p.x + p.y;
            }
        }
        __syncthreads();

        // --- gates: one (batch, unit) per thread ---
        {
            float gh[3];
#pragma unroll
            for (int g = 0; g < 3; g++) {
                const int out = bg * NROWS + g * 8 + ug;
                float s = 0.f;
#pragma unroll
                for (int p = 0; p < 16; p++) s += sh_r[out * RPITCH + p];
                gh[g] = s;
            }
            const float r = 1.f / (1.f + expf(-(gi_r + gh[0] + bias_r)));
            const float z = 1.f / (1.f + expf(-(gi_z + gh[1] + bias_z)));
            const float n = tanhf(gi_n + r * (gh[2] + bias_n));
            const float hnew = (1.f - z) * n + z * hprev;

            h_all[(hrow + t) * HD + (u0 + ug)] = hnew;
        }

        // --- grid barrier: release own flag, poll all 96 ---
        __syncthreads();                     // all h_t STG issued before release
        const unsigned target = flag_base + (unsigned)(t + 1);
        if (tid == 0) {
            asm volatile("st.release.gpu.global.u32 [%0], %1;"
                         :: "l"(&g_flags[blockIdx.x]), "r"(target) : "memory");
        }
        if (tid < 32) {
#pragma unroll
            for (int f = tid; f < NBLK; f += 32) {
                unsigned v;
                do {
                    asm volatile("ld.acquire.gpu.global.u32 %0, [%1];"
                                 : "=r"(v) : "l"(&g_flags[f]) : "memory");
                } while ((int)(v - target) < 0);
            }
        }
        __syncthreads();
    }
}

// ---------------------------------------------------------------------------
// Launch: 6 graph nodes total.
// ---------------------------------------------------------------------------
extern "C" void kernel_launch(void* const* d_in, const int* in_sizes, int n_in,
                              void* d_out, int out_size)
{
    const float* features = (const float*)d_in[0];
    // d_in[1] = padding_mask (unused by forward math)
    const float* w_ih0 = (const float*)d_in[2];
    const float* w_hh0 = (const float*)d_in[3];
    const float* b_ih0 = (const float*)d_in[4];
    const float* b_hh0 = (const float*)d_in[5];
    const float* w_ih1 = (const float*)d_in[6];
    const float* w_hh1 = (const float*)d_in[7];
    const float* b_ih1 = (const float*)d_in[8];
    const float* b_hh1 = (const float*)d_in[9];
    const float* fc_w  = (const float*)d_in[10];
    const float* fc_b  = (const float*)d_in[11];
    const float* out_w = (const float*)d_in[12];
    const float* out_b = (const float*)d_in[13];

    float *xproj, *hall, *fcb;
    cudaGetSymbolAddress((void**)&xproj, g_xproj);
    cudaGetSymbolAddress((void**)&hall,  g_hall);
    cudaGetSymbolAddress((void**)&fcb,   g_fc);

    static bool attr_set = false;
    if (!attr_set) {
        cudaFuncSetAttribute(gru_layer_persistent,
                             cudaFuncAttributeMaxDynamicSharedMemorySize,
                             (int)STEP_SMEM);
        attr_set = true;
    }

    const int M = BSZ * TLEN;                 // 32768

    // Layer 0: input projection (bias b_ih folded in)
    {
        dim3 grid(G3 / 128, M / 128);
        gemm_bias_act<0><<<grid, 256>>>(features, w_ih0, b_ih0, xproj, M, G3, DIN);
    }
    // Layer 0: full recurrence in one persistent kernel
    gru_layer_persistent<<<NBLK, 256, STEP_SMEM>>>(xproj, w_hh0, b_hh0, hall);

    // Layer 1: input projection (reads layer-0 h_all, overwrites xproj)
    {
        dim3 grid(G3 / 128, M / 128);
        gemm_bias_act<0><<<grid, 256>>>(hall, w_ih1, b_ih1, xproj, M, G3, HD);
    }
    // Layer 1: recurrence (overwrites h_all in place)
    gru_layer_persistent<<<NBLK, 256, STEP_SMEM>>>(xproj, w_hh1, b_hh1, hall);

    // fc + SELU
    {
        dim3 grid(FCN / 128, M / 128);
        gemm_bias_act<1><<<grid, 256>>>(hall, fc_w, fc_b, fcb, M, FCN, HD);
    }
    // out_proj + tanh
    {
        dim3 grid((NOUTC + 127) / 128, M / 128);
        gemm_bias_act<2><<<grid, 256>>>(fcb, out_w, out_b, (float*)d_out, M, NOUTC, FCN);
    }
}